// round 2
// baseline (speedup 1.0000x reference)
#include <cuda_runtime.h>
#include <cstdint>

#define KK 3
#define CIN 64
#define COUT 64
#define HH 128
#define WW 128
#define BB 4
#define SLAB 4104          // floats per h-slab: 4096 + 8 pad (distinct-bank offset)
#define IN_XPAD 132        // 128 + halo(2) + pad(2)
#define NTHREADS 512
#define TAP_BYTES (3 * 4096 * 4)   // 3 h-slabs of one tap in gmem (contiguous)

// Transposed weights: [tap][h][c][o], tap = ky*3+kx
__device__ float g_wt[9 * 3 * CIN * COUT];

__global__ void transpose_w_kernel(const float* __restrict__ w) {
    int idx = blockIdx.x * blockDim.x + threadIdx.x;
    if (idx >= 9 * 3 * CIN * COUT) return;
    int o   = idx & 63;
    int c   = (idx >> 6) & 63;
    int h   = (idx >> 12) % 3;
    int tap = idx / (3 * CIN * COUT);
    // source layout: [h][o][c][ky][kx]
    g_wt[idx] = w[(((h * COUT + o) * CIN + c) * 9) + tap];
}

__device__ __forceinline__ uint32_t smem_u32(const void* p) {
    uint32_t a;
    asm("{ .reg .u64 t; cvta.to.shared.u64 t, %1; cvt.u32.u64 %0, t; }" : "=r"(a) : "l"(p));
    return a;
}

__device__ __forceinline__ void mbar_init(uint32_t m, uint32_t cnt) {
    asm volatile("mbarrier.init.shared.b64 [%0], %1;" :: "r"(m), "r"(cnt) : "memory");
}
__device__ __forceinline__ void mbar_expect_tx(uint32_t m, uint32_t bytes) {
    asm volatile("mbarrier.arrive.expect_tx.shared.b64 _, [%0], %1;" :: "r"(m), "r"(bytes) : "memory");
}
__device__ __forceinline__ void bulk_cp(uint32_t dst, const void* src, uint32_t bytes, uint32_t m) {
    asm volatile("cp.async.bulk.shared::cta.global.mbarrier::complete_tx::bytes [%0], [%1], %2, [%3];"
                 :: "r"(dst), "l"(src), "r"(bytes), "r"(m) : "memory");
}
__device__ __forceinline__ void mbar_wait(uint32_t m, uint32_t parity) {
    uint32_t done;
    asm volatile("{\n\t.reg .pred p;\n\t"
                 "mbarrier.try_wait.parity.acquire.cta.shared::cta.b64 p, [%1], %2;\n\t"
                 "selp.b32 %0, 1, 0, p;\n\t}"
                 : "=r"(done) : "r"(m), "r"(parity) : "memory");
    if (!done) {
        asm volatile("{\n\t.reg .pred P1;\n\t"
                     "W_%=:\n\t"
                     "mbarrier.try_wait.parity.acquire.cta.shared::cta.b64 P1, [%0], %1, 0x989680;\n\t"
                     "@P1 bra.uni D_%=;\n\t"
                     "bra.uni W_%=;\n\t"
                     "D_%=:\n\t}" :: "r"(m), "r"(parity) : "memory");
    }
}

// accumulate 64-channel dot for one tap; slab already selected per lane (16 o)
__device__ __forceinline__ void accumulate_tap(unsigned long long acc[8],
                                               const float* __restrict__ wbase,
                                               const float* __restrict__ inrow) {
#pragma unroll 8
    for (int c = 0; c < CIN; c++) {
        float iv = inrow[c * IN_XPAD];
        unsigned long long iv2;
        asm("mov.b64 %0, {%1, %1};" : "=l"(iv2) : "f"(iv));
        const ulonglong2* wp = reinterpret_cast<const ulonglong2*>(wbase + c * COUT);
#pragma unroll
        for (int i = 0; i < 4; i++) {
            ulonglong2 wv = wp[i];
            asm("fma.rn.f32x2 %0, %1, %2, %0;" : "+l"(acc[2 * i])     : "l"(wv.x), "l"(iv2));
            asm("fma.rn.f32x2 %0, %1, %2, %0;" : "+l"(acc[2 * i + 1]) : "l"(wv.y), "l"(iv2));
        }
    }
}

__global__ __launch_bounds__(NTHREADS, 1)
void conv25d_kernel(const float* __restrict__ inp, const float* __restrict__ dep,
                    const float* __restrict__ bias, const void* __restrict__ fptr,
                    float* __restrict__ out) {
    extern __shared__ float smem[];
    float* s_in   = smem;                             // [3][CIN][IN_XPAD]  25344
    float* s_d    = s_in + 3 * CIN * IN_XPAD;         // [3][IN_XPAD]       396
    float* s_zero = s_d + 3 * IN_XPAD;                // [SLAB]             4104
    float* s_wbuf = s_zero + SLAB;                    // [2][3*SLAB]        24624
    float* s_end  = s_wbuf + 2 * 3 * SLAB;
    unsigned long long* s_mbar = reinterpret_cast<unsigned long long*>(s_end);  // [2]

    const int tid = threadIdx.x;
    const int y   = blockIdx.x;
    const int b   = blockIdx.y;
    const int x   = tid & 127;     // pixel column
    const int og  = tid >> 7;      // o-group: 16 channels each

    const uint32_t mb0 = smem_u32(&s_mbar[0]);
    const uint32_t mb1 = smem_u32(&s_mbar[1]);
    const uint32_t wb0 = smem_u32(s_wbuf);
    const uint32_t slab_bytes = SLAB * 4;

    if (tid == 0) { mbar_init(mb0, 1); mbar_init(mb1, 1); }
    __syncthreads();
    if (tid == 0) {
        asm volatile("fence.proxy.async.shared::cta;" ::: "memory");
        // prologue: tap 0 into buffer 0
        mbar_expect_tx(mb0, TAP_BYTES);
#pragma unroll
        for (int h = 0; h < 3; h++)
            bulk_cp(wb0 + h * slab_bytes, g_wt + h * 4096, 4096 * 4, mb0);
    }

    // robust read of scalar f (int or float bits)
    unsigned fu = *reinterpret_cast<const unsigned*>(fptr);
    float fval = (fu > 0u && fu < (1u << 24)) ? (float)fu : __uint_as_float(fu);

    // stage input rows y-1..y+1, all channels, zero halo (overlaps with bulk copy)
    const float* inb = inp + ((long)b * CIN) * HH * WW;
    for (int i = tid; i < 3 * CIN * IN_XPAD; i += NTHREADS) {
        int xx = i % IN_XPAD;
        int c  = (i / IN_XPAD) % CIN;
        int r  = i / (IN_XPAD * CIN);
        int gx = xx - 1, gy = y + r - 1;
        float v = 0.f;
        if ((unsigned)gx < (unsigned)WW && (unsigned)gy < (unsigned)HH)
            v = inb[(c * HH + gy) * WW + gx];
        s_in[i] = v;
    }
    const float* db = dep + (long)b * HH * WW;
    for (int i = tid; i < 3 * IN_XPAD; i += NTHREADS) {
        int xx = i % IN_XPAD, r = i / IN_XPAD;
        int gx = xx - 1, gy = y + r - 1;
        float v = 0.f;
        if ((unsigned)gx < (unsigned)WW && (unsigned)gy < (unsigned)HH)
            v = db[gy * WW + gx];
        s_d[i] = v;
    }
    for (int i = tid; i < SLAB; i += NTHREADS) s_zero[i] = 0.f;

    // accumulators: 8 f32x2 pairs over 16 o, initialized with bias
    unsigned long long acc[8];
    {
        const float2* bp = reinterpret_cast<const float2*>(bias + og * 16);
#pragma unroll
        for (int i = 0; i < 8; i++) {
            float2 bv = bp[i];
            asm("mov.b64 %0, {%1, %2};" : "=l"(acc[i]) : "f"(bv.x), "f"(bv.y));
        }
    }
    __syncthreads();

    // per-pixel bin boundaries, replicating reference float ops exactly
    const float d0   = s_d[IN_XPAD + x + 1];
    const float s0   = __fdiv_rn(d0, fval);
    const float half = __fmul_rn(s0, 0.5f);
    float lo[3], hi[3];
#pragma unroll
    for (int h = 0; h < 3; h++) {
        float z0 = __fadd_rn(d0, __fmul_rn((float)(h - 1), s0));
        lo[h] = __fsub_rn(z0, half);
        hi[h] = __fadd_rn(z0, half);
    }

#pragma unroll 1
    for (int tap = 0; tap < 9; tap++) {
        // issue async copy of next tap's weights into the other buffer
        if (tap < 8 && tid == 0) {
            uint32_t mbn = ((tap + 1) & 1) ? mb1 : mb0;
            uint32_t wbn = wb0 + ((tap + 1) & 1) * 3 * slab_bytes;
            const float* src = g_wt + (tap + 1) * 3 * 4096;
            mbar_expect_tx(mbn, TAP_BYTES);
#pragma unroll
            for (int h = 0; h < 3; h++)
                bulk_cp(wbn + h * slab_bytes, src + h * 4096, 4096 * 4, mbn);
        }
        // wait for current tap's weights
        mbar_wait((tap & 1) ? mb1 : mb0, (tap >> 1) & 1);

        const int ky = tap / 3, kx = tap % 3;
        const float dw = s_d[ky * IN_XPAD + x + kx];
        int ha = 3, hb = 3;
#pragma unroll
        for (int h = 2; h >= 0; h--) {
            if (dw >= lo[h] && dw < hi[h]) { hb = ha; ha = h; }
        }
        const float* bufb  = s_wbuf + (tap & 1) * 3 * SLAB;
        const float* inrow = s_in + ky * CIN * IN_XPAD + (x + kx);

        const float* slabA = (ha < 3) ? (bufb + ha * SLAB) : s_zero;
        accumulate_tap(acc, slabA + og * 16, inrow);

        // rare float-boundary overlap: reference's mask-sum double-counts, so do we
        unsigned m = __ballot_sync(0xffffffffu, hb != 3);
        if (m) {
            const float* slabB = (hb < 3) ? (bufb + hb * SLAB) : s_zero;
            accumulate_tap(acc, slabB + og * 16, inrow);
        }

        __syncthreads();  // all warps done with this buffer before it's re-filled
    }

    // store 16 output channels for this pixel
    float* ob = out + (((long)b * COUT + og * 16) * HH + y) * WW + x;
#pragma unroll
    for (int i = 0; i < 8; i++) {
        float vlo, vhi;
        asm("mov.b64 {%0, %1}, %2;" : "=f"(vlo), "=f"(vhi) : "l"(acc[i]));
        ob[(2 * i) * HH * WW]     = vlo;
        ob[(2 * i + 1) * HH * WW] = vhi;
    }
}

extern "C" void kernel_launch(void* const* d_in, const int* in_sizes, int n_in,
                              void* d_out, int out_size) {
    const float* inputs = (const float*)d_in[0];
    const float* depth  = (const float*)d_in[1];
    const float* weight = (const float*)d_in[2];
    const float* bias   = (const float*)d_in[3];
    const void*  f      = d_in[4];
    float* out = (float*)d_out;

    transpose_w_kernel<<<(9 * 3 * CIN * COUT + 255) / 256, 256>>>(weight);

    size_t smem_bytes = (size_t)(3 * CIN * IN_XPAD + 3 * IN_XPAD + SLAB + 2 * 3 * SLAB) * sizeof(float)
                        + 2 * sizeof(unsigned long long) + 16;
    cudaFuncSetAttribute(conv25d_kernel, cudaFuncAttributeMaxDynamicSharedMemorySize,
                         (int)smem_bytes);

    dim3 grid(HH, BB);
    conv25d_kernel<<<grid, NTHREADS, smem_bytes>>>(inputs, depth, bias, f, out);
}

// round 4
// speedup vs baseline: 3.6481x; 3.6481x over previous
#include <cuda_runtime.h>
#include <cstdint>

#define CIN 64
#define COUT 64
#define HH 128
#define WW 128
#define BB 4
#define NTHREADS 256
#define XPAD 136            // s_in row width: bank = (8c + x) % 32 -> conflict-free frags

// ---- smem byte offsets ----
#define OFF_FULL  0         // 2 x 8B mbarrier (weight group full)
#define OFF_EMPTY 16        // 2 x 8B mbarrier (weight group empty)
#define OFF_D     64        // 3 x 136 floats
#define OFF_LO    1696      // 3 x 128 floats
#define OFF_HI    3232      // 3 x 128 floats
#define OFF_BIAS  4768      // 64 floats
#define OFF_IN    5120      // 3 x 64 x 136 u32 (tf32 bits) = 104448 B
#define OFF_W     109568    // 2 groups x 3 h x 16384 B = 98304 B
#define SMEM_TOTAL 207872
#define WGROUP_BYTES 49152  // 3 h-tiles

// Fragment-ordered tf32 weights: [tile=tap*3+h][kc8][nt8][lane32][j2]
__device__ uint32_t g_wf[27 * 4096];

__device__ __forceinline__ uint32_t f2tf32(float v) {
    uint32_t u;
    asm("cvt.rna.tf32.f32 %0, %1;" : "=r"(u) : "f"(v));
    return u;
}

__global__ void prep_w_kernel(const float* __restrict__ w) {
    int idx = blockIdx.x * blockDim.x + threadIdx.x;
    if (idx >= 27 * 4096) return;
    int j    = idx & 1;
    int lane = (idx >> 1) & 31;
    int nt   = (idx >> 6) & 7;
    int kc   = (idx >> 9) & 7;
    int tile = idx >> 12;
    int h = tile % 3, tap = tile / 3;
    int c = kc * 8 + (lane & 3) + j * 4;   // K within tile (cin)
    int o = nt * 8 + (lane >> 2);          // N (cout)
    // source layout: [h][o][c][ky][kx]
    float v = w[(((h * COUT + o) * CIN + c) * 9) + tap];
    g_wf[idx] = f2tf32(v);
}

// ---- PTX helpers (non-'a' features only) ----
__device__ __forceinline__ uint32_t smem_u32(const void* p) {
    uint32_t a;
    asm("{ .reg .u64 t; cvta.to.shared.u64 t, %1; cvt.u32.u64 %0, t; }" : "=r"(a) : "l"(p));
    return a;
}
__device__ __forceinline__ void mbar_init(uint32_t m, uint32_t cnt) {
    asm volatile("mbarrier.init.shared.b64 [%0], %1;" :: "r"(m), "r"(cnt) : "memory");
}
__device__ __forceinline__ void mbar_arrive(uint32_t m) {
    asm volatile("mbarrier.arrive.shared.b64 _, [%0];" :: "r"(m) : "memory");
}
__device__ __forceinline__ void mbar_expect_tx(uint32_t m, uint32_t bytes) {
    asm volatile("mbarrier.arrive.expect_tx.shared.b64 _, [%0], %1;" :: "r"(m), "r"(bytes) : "memory");
}
__device__ __forceinline__ void bulk_cp(uint32_t dst, const void* src, uint32_t bytes, uint32_t m) {
    asm volatile("cp.async.bulk.shared::cta.global.mbarrier::complete_tx::bytes [%0], [%1], %2, [%3];"
                 :: "r"(dst), "l"(src), "r"(bytes), "r"(m) : "memory");
}
__device__ __forceinline__ void mbar_wait(uint32_t m, uint32_t parity) {
    uint32_t done;
    asm volatile("{\n\t.reg .pred p;\n\t"
                 "mbarrier.try_wait.parity.acquire.cta.shared::cta.b64 p, [%1], %2;\n\t"
                 "selp.b32 %0, 1, 0, p;\n\t}"
                 : "=r"(done) : "r"(m), "r"(parity) : "memory");
    if (!done) {
        asm volatile("{\n\t.reg .pred P1;\n\t"
                     "W_%=:\n\t"
                     "mbarrier.try_wait.parity.acquire.cta.shared::cta.b64 P1, [%0], %1, 0x989680;\n\t"
                     "@P1 bra.uni D_%=;\n\t"
                     "bra.uni W_%=;\n\t"
                     "D_%=:\n\t}" :: "r"(m), "r"(parity) : "memory");
    }
}
__device__ __forceinline__ void mma_tf32(float& d0, float& d1, float& d2, float& d3,
                                         uint32_t a0, uint32_t a1, uint32_t a2, uint32_t a3,
                                         uint32_t b0, uint32_t b1) {
    asm volatile("mma.sync.aligned.m16n8k8.row.col.f32.tf32.tf32.f32 "
                 "{%0,%1,%2,%3}, {%4,%5,%6,%7}, {%8,%9}, {%0,%1,%2,%3};"
                 : "+f"(d0), "+f"(d1), "+f"(d2), "+f"(d3)
                 : "r"(a0), "r"(a1), "r"(a2), "r"(a3), "r"(b0), "r"(b1));
}

__global__ __launch_bounds__(NTHREADS, 1)
void conv25d_mma_kernel(const float* __restrict__ inp, const float* __restrict__ dep,
                        const float* __restrict__ bias, const void* __restrict__ fptr,
                        float* __restrict__ out) {
    extern __shared__ char smem[];
    const uint32_t sb = smem_u32(smem);
    const int tid  = threadIdx.x;
    const int wid  = tid >> 5;
    const int lane = tid & 31;
    const int mw   = wid & 3;     // M warp: px rows [mw*32, mw*32+32)
    const int nw   = wid >> 2;    // N warp: o cols  [nw*32, nw*32+32)
    const int y    = blockIdx.x;
    const int b    = blockIdx.y;

    float*     s_d    = (float*)(smem + OFF_D);
    float*     s_lo   = (float*)(smem + OFF_LO);
    float*     s_hi   = (float*)(smem + OFF_HI);
    float*     s_bias = (float*)(smem + OFF_BIAS);
    uint32_t*  s_in   = (uint32_t*)(smem + OFF_IN);
    const uint32_t mb_full  = sb + OFF_FULL;
    const uint32_t mb_empty = sb + OFF_EMPTY;
    const uint32_t wsm      = sb + OFF_W;

    if (tid == 0) {
        mbar_init(mb_full + 0, 1);   mbar_init(mb_full + 8, 1);
        mbar_init(mb_empty + 0, NTHREADS); mbar_init(mb_empty + 8, NTHREADS);
    }
    __syncthreads();
    if (tid == 0) {
        asm volatile("fence.proxy.async.shared::cta;" ::: "memory");
        // prefetch weight groups for tap 0 and tap 1
        for (int g = 0; g < 2; g++) {
            mbar_expect_tx(mb_full + 8 * g, WGROUP_BYTES);
            for (int h = 0; h < 3; h++)
                bulk_cp(wsm + g * WGROUP_BYTES + h * 16384,
                        g_wf + (g * 3 + h) * 4096, 16384, mb_full + 8 * g);
        }
    }

    // scalar f (int or float bits)
    unsigned fu = *reinterpret_cast<const unsigned*>(fptr);
    float fval = (fu > 0u && fu < (1u << 24)) ? (float)fu : __uint_as_float(fu);

    // stage depth rows + bin bounds + bias
    const float* db = dep + (long)b * HH * WW;
    for (int i = tid; i < 3 * XPAD; i += NTHREADS) {
        int xx = i % XPAD, r = i / XPAD;
        int gx = xx - 1, gy = y + r - 1;
        float v = 0.f;
        if ((unsigned)gx < (unsigned)WW && (unsigned)gy < (unsigned)HH) v = db[gy * WW + gx];
        s_d[i] = v;
    }
    if (tid < 128) {
        float d0 = db[y * WW + tid];
        float s0 = __fdiv_rn(d0, fval);
        float hv = __fmul_rn(s0, 0.5f);
#pragma unroll
        for (int h = 0; h < 3; h++) {
            float z0 = __fadd_rn(d0, __fmul_rn((float)(h - 1), s0));
            s_lo[h * 128 + tid] = __fsub_rn(z0, hv);
            s_hi[h * 128 + tid] = __fadd_rn(z0, hv);
        }
    }
    if (tid < 64) s_bias[tid] = bias[tid];

    // stage input rows y-1..y+1, tf32-rounded bits, zero halo
    const float* inb = inp + ((long)b * CIN) * HH * WW;
    for (int i = tid; i < 3 * CIN * XPAD; i += NTHREADS) {
        int xx = i % XPAD;
        int c  = (i / XPAD) % CIN;
        int r  = i / (XPAD * CIN);
        int gx = xx - 1, gy = y + r - 1;
        uint32_t u = 0u;
        if ((unsigned)gx < (unsigned)WW && (unsigned)gy < (unsigned)HH)
            u = f2tf32(inb[(c * HH + gy) * WW + gx]);
        s_in[i] = u;
    }
    __syncthreads();

    const int px_base = mw * 32 + (lane >> 2);
    // preload per-thread bin bounds for the 4 px rows (offsets 0,8,16,24)
    float lo_r[3][4], hi_r[3][4];
#pragma unroll
    for (int i = 0; i < 4; i++) {
        int pxr = px_base + i * 8;
#pragma unroll
        for (int h = 0; h < 3; h++) {
            lo_r[h][i] = s_lo[h * 128 + pxr];
            hi_r[h][i] = s_hi[h * 128 + pxr];
        }
    }

    float d[2][4][4];   // [mt][nt][reg]
#pragma unroll
    for (int mt = 0; mt < 2; mt++)
#pragma unroll
        for (int nt = 0; nt < 4; nt++)
#pragma unroll
            for (int r = 0; r < 4; r++) d[mt][nt][r] = 0.f;

#pragma unroll 1
    for (int tap = 0; tap < 9; tap++) {
        const int g  = tap & 1;
        const int ph = (tap >> 1) & 1;
        mbar_wait(mb_full + 8 * g, ph);

        const int ky = tap / 3, kx = tap % 3;
        // per-row masks for this tap (full-word masks)
        uint32_t msk[3][4];
#pragma unroll
        for (int i = 0; i < 4; i++) {
            float dw = s_d[ky * XPAD + px_base + i * 8 + kx];
#pragma unroll
            for (int h = 0; h < 3; h++)
                msk[h][i] = (dw >= lo_r[h][i] && dw < hi_r[h][i]) ? 0xFFFFFFFFu : 0u;
        }

        const uint32_t* abase = s_in + ky * CIN * XPAD + px_base + kx;
        const uint2*    bgrp  = (const uint2*)(smem + OFF_W + g * WGROUP_BYTES);

#pragma unroll 1
        for (int kc = 0; kc < 8; kc++) {
            const int c0 = kc * 8 + (lane & 3);
            uint32_t ar[2][4];
#pragma unroll
            for (int j = 0; j < 2; j++)
#pragma unroll
                for (int i = 0; i < 4; i++)
                    ar[j][i] = abase[(c0 + 4 * j) * XPAD + i * 8];

#pragma unroll
            for (int h = 0; h < 3; h++) {
                uint32_t am[2][4];
#pragma unroll
                for (int j = 0; j < 2; j++)
#pragma unroll
                    for (int i = 0; i < 4; i++)
                        am[j][i] = ar[j][i] & msk[h][i];

                const uint2* bp = bgrp + (h * 2048) + (kc * 8 + nw * 4) * 32 + lane;
                uint2 bf[4];
#pragma unroll
                for (int nt = 0; nt < 4; nt++) bf[nt] = bp[nt * 32];

#pragma unroll
                for (int mt = 0; mt < 2; mt++)
#pragma unroll
                    for (int nt = 0; nt < 4; nt++)
                        mma_tf32(d[mt][nt][0], d[mt][nt][1], d[mt][nt][2], d[mt][nt][3],
                                 am[0][2 * mt], am[0][2 * mt + 1],
                                 am[1][2 * mt], am[1][2 * mt + 1],
                                 bf[nt].x, bf[nt].y);
            }
        }

        mbar_arrive(mb_empty + 8 * g);
        if (tid == 0 && tap + 2 < 9) {
            mbar_wait(mb_empty + 8 * g, ph);
            mbar_expect_tx(mb_full + 8 * g, WGROUP_BYTES);
            for (int h = 0; h < 3; h++)
                bulk_cp(wsm + g * WGROUP_BYTES + h * 16384,
                        g_wf + ((tap + 2) * 3 + h) * 4096, 16384, mb_full + 8 * g);
        }
    }

    // epilogue: bias + store. out[b][o][y][px]
    float* ob = out + ((long)b * COUT * HH + y) * WW;
#pragma unroll
    for (int mt = 0; mt < 2; mt++) {
        int pxr = mw * 32 + mt * 16 + (lane >> 2);
#pragma unroll
        for (int nt = 0; nt < 4; nt++) {
            int o = nw * 32 + nt * 8 + 2 * (lane & 3);
            float b0 = s_bias[o], b1 = s_bias[o + 1];
            float* p0 = ob + (long)o * HH * WW + pxr;
            float* p1 = p0 + HH * WW;
            p0[0] = d[mt][nt][0] + b0;
            p1[0] = d[mt][nt][1] + b1;
            p0[8] = d[mt][nt][2] + b0;
            p1[8] = d[mt][nt][3] + b1;
        }
    }
}

extern "C" void kernel_launch(void* const* d_in, const int* in_sizes, int n_in,
                              void* d_out, int out_size) {
    const float* inputs = (const float*)d_in[0];
    const float* depth  = (const float*)d_in[1];
    const float* weight = (const float*)d_in[2];
    const float* bias   = (const float*)d_in[3];
    const void*  f      = d_in[4];
    float* out = (float*)d_out;

    prep_w_kernel<<<(27 * 4096 + 255) / 256, 256>>>(weight);

    cudaFuncSetAttribute(conv25d_mma_kernel, cudaFuncAttributeMaxDynamicSharedMemorySize,
                         SMEM_TOTAL);
    dim3 grid(HH, BB);
    conv25d_mma_kernel<<<grid, NTHREADS, SMEM_TOTAL>>>(inputs, depth, bias, f, out);
}

// round 5
// speedup vs baseline: 4.0741x; 1.1168x over previous
#include <cuda_runtime.h>
#include <cstdint>

#define CIN 64
#define COUT 64
#define HH 128
#define WW 128
#define BB 4
#define NTHREADS 512
#define XPAD 136            // s_in row width: bank = (8c + x) % 32 -> conflict-free frags
#define NSLOT 4             // weight ring slots (16 KB h-tiles)

// ---- smem byte offsets ----
#define OFF_FULL  0         // 4 x 8B
#define OFF_EMPTY 32        // 4 x 8B
#define OFF_D     64        // 4 x 136 floats
#define OFF_LO    2240      // 3 x 256 floats
#define OFF_HI    5312      // 3 x 256 floats
#define OFF_BIAS  8384      // 64 floats
#define OFF_IN    8704      // 4 rows x 64 c x 136 u32 = 139264 B
#define OFF_W     147968    // 4 slots x 16384 B = 65536 B
#define SMEM_TOTAL 213504
#define TILE_BYTES 16384

// Fragment-ordered tf32 weights: [tile=tap*3+h][kc8][nt8][lane32][j2]
__device__ uint32_t g_wf[27 * 4096];

__device__ __forceinline__ uint32_t f2tf32(float v) {
    uint32_t u;
    asm("cvt.rna.tf32.f32 %0, %1;" : "=r"(u) : "f"(v));
    return u;
}

__global__ void prep_w_kernel(const float* __restrict__ w) {
    int idx = blockIdx.x * blockDim.x + threadIdx.x;
    if (idx >= 27 * 4096) return;
    int j    = idx & 1;
    int lane = (idx >> 1) & 31;
    int nt   = (idx >> 6) & 7;
    int kc   = (idx >> 9) & 7;
    int tile = idx >> 12;
    int h = tile % 3, tap = tile / 3;
    int c = kc * 8 + (lane & 3) + j * 4;
    int o = nt * 8 + (lane >> 2);
    // source layout: [h][o][c][ky][kx]
    float v = w[(((h * COUT + o) * CIN + c) * 9) + tap];
    g_wf[idx] = f2tf32(v);
}

// ---- PTX helpers ----
__device__ __forceinline__ uint32_t smem_u32(const void* p) {
    uint32_t a;
    asm("{ .reg .u64 t; cvta.to.shared.u64 t, %1; cvt.u32.u64 %0, t; }" : "=r"(a) : "l"(p));
    return a;
}
__device__ __forceinline__ void mbar_init(uint32_t m, uint32_t cnt) {
    asm volatile("mbarrier.init.shared.b64 [%0], %1;" :: "r"(m), "r"(cnt) : "memory");
}
__device__ __forceinline__ void mbar_arrive(uint32_t m) {
    asm volatile("mbarrier.arrive.shared.b64 _, [%0];" :: "r"(m) : "memory");
}
__device__ __forceinline__ void mbar_expect_tx(uint32_t m, uint32_t bytes) {
    asm volatile("mbarrier.arrive.expect_tx.shared.b64 _, [%0], %1;" :: "r"(m), "r"(bytes) : "memory");
}
__device__ __forceinline__ void bulk_cp(uint32_t dst, const void* src, uint32_t bytes, uint32_t m) {
    asm volatile("cp.async.bulk.shared::cta.global.mbarrier::complete_tx::bytes [%0], [%1], %2, [%3];"
                 :: "r"(dst), "l"(src), "r"(bytes), "r"(m) : "memory");
}
__device__ __forceinline__ void mbar_wait(uint32_t m, uint32_t parity) {
    uint32_t done;
    asm volatile("{\n\t.reg .pred p;\n\t"
                 "mbarrier.try_wait.parity.acquire.cta.shared::cta.b64 p, [%1], %2;\n\t"
                 "selp.b32 %0, 1, 0, p;\n\t}"
                 : "=r"(done) : "r"(m), "r"(parity) : "memory");
    if (!done) {
        asm volatile("{\n\t.reg .pred P1;\n\t"
                     "W_%=:\n\t"
                     "mbarrier.try_wait.parity.acquire.cta.shared::cta.b64 P1, [%0], %1, 0x989680;\n\t"
                     "@P1 bra.uni D_%=;\n\t"
                     "bra.uni W_%=;\n\t"
                     "D_%=:\n\t}" :: "r"(m), "r"(parity) : "memory");
    }
}
__device__ __forceinline__ void mma_tf32(float& d0, float& d1, float& d2, float& d3,
                                         uint32_t a0, uint32_t a1, uint32_t a2, uint32_t a3,
                                         uint32_t b0, uint32_t b1) {
    asm volatile("mma.sync.aligned.m16n8k8.row.col.f32.tf32.tf32.f32 "
                 "{%0,%1,%2,%3}, {%4,%5,%6,%7}, {%8,%9}, {%0,%1,%2,%3};"
                 : "+f"(d0), "+f"(d1), "+f"(d2), "+f"(d3)
                 : "r"(a0), "r"(a1), "r"(a2), "r"(a3), "r"(b0), "r"(b1));
}

__global__ __launch_bounds__(NTHREADS, 1)
void conv25d_mma_kernel(const float* __restrict__ inp, const float* __restrict__ dep,
                        const float* __restrict__ bias, const void* __restrict__ fptr,
                        float* __restrict__ out) {
    extern __shared__ char smem[];
    const uint32_t sb = smem_u32(smem);
    const int tid  = threadIdx.x;
    const int wid  = tid >> 5;
    const int lane = tid & 31;
    const int mw   = wid & 7;      // M warp: global px rows [mw*32, mw*32+32)
    const int nw   = wid >> 3;     // N warp: o cols [nw*32, nw*32+32)
    const int yl   = mw >> 2;      // local y row of this warp (0 or 1)
    const int pxl  = (mw & 3) * 32 + (lane >> 2);   // px within row
    const int y0   = blockIdx.x * 2;
    const int b    = blockIdx.y;

    float*     s_d    = (float*)(smem + OFF_D);
    float*     s_lo   = (float*)(smem + OFF_LO);
    float*     s_hi   = (float*)(smem + OFF_HI);
    float*     s_bias = (float*)(smem + OFF_BIAS);
    uint32_t*  s_in   = (uint32_t*)(smem + OFF_IN);
    const uint32_t mb_full  = sb + OFF_FULL;
    const uint32_t mb_empty = sb + OFF_EMPTY;
    const uint32_t wsm      = sb + OFF_W;

    if (tid == 0) {
        for (int s = 0; s < NSLOT; s++) {
            mbar_init(mb_full + 8 * s, 1);
            mbar_init(mb_empty + 8 * s, 16);   // one arrive per warp
        }
    }
    __syncthreads();
    if (tid == 0) {
        asm volatile("fence.proxy.async.shared::cta;" ::: "memory");
        // prologue: tiles 0..3 into slots 0..3
        for (int t = 0; t < NSLOT; t++) {
            mbar_expect_tx(mb_full + 8 * t, TILE_BYTES);
            bulk_cp(wsm + t * TILE_BYTES, g_wf + t * 4096, TILE_BYTES, mb_full + 8 * t);
        }
    }

    // scalar f (int or float bits)
    unsigned fu = *reinterpret_cast<const unsigned*>(fptr);
    float fval = (fu > 0u && fu < (1u << 24)) ? (float)fu : __uint_as_float(fu);

    // depth rows y0-1 .. y0+2 (padded), bin bounds for 2 output rows, bias
    const float* db = dep + (long)b * HH * WW;
    for (int i = tid; i < 4 * XPAD; i += NTHREADS) {
        int xx = i % XPAD, r = i / XPAD;
        int gx = xx - 1, gy = y0 + r - 1;
        float v = 0.f;
        if ((unsigned)gx < (unsigned)WW && (unsigned)gy < (unsigned)HH) v = db[gy * WW + gx];
        s_d[i] = v;
    }
    if (tid < 256) {
        int x = tid & 127, yy = y0 + (tid >> 7);
        float d0 = db[yy * WW + x];
        float s0 = __fdiv_rn(d0, fval);
        float hv = __fmul_rn(s0, 0.5f);
#pragma unroll
        for (int h = 0; h < 3; h++) {
            float z0 = __fadd_rn(d0, __fmul_rn((float)(h - 1), s0));
            s_lo[h * 256 + tid] = __fsub_rn(z0, hv);
            s_hi[h * 256 + tid] = __fadd_rn(z0, hv);
        }
    }
    if (tid < 64) s_bias[tid] = bias[tid];

    // stage input rows y0-1 .. y0+2, tf32 bits, zero halo
    const float* inb = inp + ((long)b * CIN) * HH * WW;
    for (int i = tid; i < 4 * CIN * XPAD; i += NTHREADS) {
        int xx = i % XPAD;
        int c  = (i / XPAD) % CIN;
        int r  = i / (XPAD * CIN);
        int gx = xx - 1, gy = y0 + r - 1;
        uint32_t u = 0u;
        if ((unsigned)gx < (unsigned)WW && (unsigned)gy < (unsigned)HH)
            u = f2tf32(inb[(c * HH + gy) * WW + gx]);
        s_in[i] = u;
    }
    __syncthreads();

    // preload per-thread bin bounds (global px = mw*32 + lane>>2 + i*8)
    float lo_r[3][4], hi_r[3][4];
#pragma unroll
    for (int i = 0; i < 4; i++) {
        int pg = mw * 32 + (lane >> 2) + i * 8;
#pragma unroll
        for (int h = 0; h < 3; h++) {
            lo_r[h][i] = s_lo[h * 256 + pg];
            hi_r[h][i] = s_hi[h * 256 + pg];
        }
    }

    float d[2][4][4];
#pragma unroll
    for (int mt = 0; mt < 2; mt++)
#pragma unroll
        for (int nt = 0; nt < 4; nt++)
#pragma unroll
            for (int r = 0; r < 4; r++) d[mt][nt][r] = 0.f;

#pragma unroll 1
    for (int tap = 0; tap < 9; tap++) {
        const int ky = tap / 3, kx = tap % 3;

        // wait all 3 h-tiles for this tap
        const uint2* bh[3];
#pragma unroll
        for (int h = 0; h < 3; h++) {
            int T = 3 * tap + h, s = T & 3;
            mbar_wait(mb_full + 8 * s, (T >> 2) & 1);
            bh[h] = (const uint2*)(smem + OFF_W + s * TILE_BYTES) + (nw * 4) * 32 + lane;
        }

        // per-row masks for this tap
        uint32_t msk[3][4];
#pragma unroll
        for (int i = 0; i < 4; i++) {
            float dw = s_d[(yl + ky) * XPAD + pxl + i * 8 + kx];
#pragma unroll
            for (int h = 0; h < 3; h++)
                msk[h][i] = (dw >= lo_r[h][i] && dw < hi_r[h][i]) ? 0xFFFFFFFFu : 0u;
        }

        const uint32_t* abase = s_in + (yl + ky) * CIN * XPAD + pxl + kx;

#pragma unroll 1
        for (int kc = 0; kc < 8; kc++) {
            const int c0 = kc * 8 + (lane & 3);
            uint32_t ar[2][4];
#pragma unroll
            for (int j = 0; j < 2; j++)
#pragma unroll
                for (int i = 0; i < 4; i++)
                    ar[j][i] = abase[(c0 + 4 * j) * XPAD + i * 8];

#pragma unroll
            for (int h = 0; h < 3; h++) {
                uint32_t am[2][4];
#pragma unroll
                for (int j = 0; j < 2; j++)
#pragma unroll
                    for (int i = 0; i < 4; i++)
                        am[j][i] = ar[j][i] & msk[h][i];

                const uint2* bp = bh[h] + (kc * 8) * 32;
                uint2 bf[4];
#pragma unroll
                for (int nt = 0; nt < 4; nt++) bf[nt] = bp[nt * 32];

#pragma unroll
                for (int mt = 0; mt < 2; mt++)
#pragma unroll
                    for (int nt = 0; nt < 4; nt++)
                        mma_tf32(d[mt][nt][0], d[mt][nt][1], d[mt][nt][2], d[mt][nt][3],
                                 am[0][2 * mt], am[0][2 * mt + 1],
                                 am[1][2 * mt], am[1][2 * mt + 1],
                                 bf[nt].x, bf[nt].y);
            }
        }

        // release the 3 slots (one arrive per warp)
        if (lane == 0) {
#pragma unroll
            for (int h = 0; h < 3; h++) mbar_arrive(mb_empty + 8 * ((3 * tap + h) & 3));
        }
        // producer: prefetch next tap's tiles as slots free
        if (tid == 0 && tap < 8) {
#pragma unroll
            for (int h = 0; h < 3; h++) {
                int T = 3 * (tap + 1) + h;
                if (T < NSLOT || T >= 27) continue;
                int s = T & 3;
                mbar_wait(mb_empty + 8 * s, ((T >> 2) - 1) & 1);
                mbar_expect_tx(mb_full + 8 * s, TILE_BYTES);
                bulk_cp(wsm + s * TILE_BYTES, g_wf + T * 4096, TILE_BYTES, mb_full + 8 * s);
            }
        }
    }

    // epilogue: bias + store. out[b][o][y0+yl][px]
    float* ob = out + ((long)b * COUT * HH + (y0 + yl)) * WW;
#pragma unroll
    for (int mt = 0; mt < 2; mt++) {
        int pxr = (mw & 3) * 32 + mt * 16 + (lane >> 2);
#pragma unroll
        for (int nt = 0; nt < 4; nt++) {
            int o = nw * 32 + nt * 8 + 2 * (lane & 3);
            float b0 = s_bias[o], b1 = s_bias[o + 1];
            float* p0 = ob + (long)o * HH * WW + pxr;
            float* p1 = p0 + HH * WW;
            p0[0] = d[mt][nt][0] + b0;
            p1[0] = d[mt][nt][1] + b1;
            p0[8] = d[mt][nt][2] + b0;
            p1[8] = d[mt][nt][3] + b1;
        }
    }
}

extern "C" void kernel_launch(void* const* d_in, const int* in_sizes, int n_in,
                              void* d_out, int out_size) {
    const float* inputs = (const float*)d_in[0];
    const float* depth  = (const float*)d_in[1];
    const float* weight = (const float*)d_in[2];
    const float* bias   = (const float*)d_in[3];
    const void*  f      = d_in[4];
    float* out = (float*)d_out;

    prep_w_kernel<<<(27 * 4096 + 255) / 256, 256>>>(weight);

    cudaFuncSetAttribute(conv25d_mma_kernel, cudaFuncAttributeMaxDynamicSharedMemorySize,
                         SMEM_TOTAL);
    dim3 grid(HH / 2, BB);
    conv25d_mma_kernel<<<grid, NTHREADS, SMEM_TOTAL>>>(inputs, depth, bias, f, out);
}

// round 6
// speedup vs baseline: 7.3262x; 1.7982x over previous
#include <cuda_runtime.h>
#include <cuda_fp16.h>
#include <cstdint>

#define CIN 64
#define COUT 64
#define HH 128
#define WW 128
#define BB 4
#define NTHREADS 512
#define XPAD 136            // row width in half2 words: bank=(8*c2+x)%32 conflict-free
#define NSLOT 8             // weight ring slots (8 KB h-tiles)
#define TILE_BYTES 8192

// ---- smem byte offsets ----
#define OFF_FULL  0         // 8 x 8B
#define OFF_EMPTY 64        // 8 x 8B
#define OFF_D     128       // 4 x 136 floats
#define OFF_LO    2304      // 3 x 256 floats
#define OFF_HI    5376      // 3 x 256 floats
#define OFF_BIAS  8448      // 64 floats
#define OFF_IN    8704      // 4 rows x 32 c2 x 136 u32 (half2) = 69632 B
#define OFF_W     78336     // 8 slots x 8192 B
#define SMEM_TOTAL 143872

// Fragment-ordered f16 weights: [tile=tap*3+h][kc4][nt8][lane32][j2] (u32 = half2)
__device__ uint32_t g_wf[27 * 2048];

__global__ void prep_w_kernel(const float* __restrict__ w) {
    int idx = blockIdx.x * blockDim.x + threadIdx.x;
    if (idx >= 27 * 2048) return;
    int j    = idx & 1;
    int lane = (idx >> 1) & 31;
    int nt   = (idx >> 6) & 7;
    int kc   = (idx >> 9) & 3;
    int tile = idx >> 11;
    int h = tile % 3, tap = tile / 3;
    int k0 = kc * 16 + (lane & 3) * 2 + j * 8;   // K (cin) of first half
    int o  = nt * 8 + (lane >> 2);
    // source layout: [h][o][c][ky][kx]
    float v0 = w[(((h * COUT + o) * CIN + k0) * 9) + tap];
    float v1 = w[(((h * COUT + o) * CIN + k0 + 1) * 9) + tap];
    __half2 p = __floats2half2_rn(v0, v1);
    g_wf[idx] = *reinterpret_cast<uint32_t*>(&p);
}

// ---- PTX helpers ----
__device__ __forceinline__ uint32_t smem_u32(const void* p) {
    uint32_t a;
    asm("{ .reg .u64 t; cvta.to.shared.u64 t, %1; cvt.u32.u64 %0, t; }" : "=r"(a) : "l"(p));
    return a;
}
__device__ __forceinline__ void mbar_init(uint32_t m, uint32_t cnt) {
    asm volatile("mbarrier.init.shared.b64 [%0], %1;" :: "r"(m), "r"(cnt) : "memory");
}
__device__ __forceinline__ void mbar_arrive(uint32_t m) {
    asm volatile("mbarrier.arrive.shared.b64 _, [%0];" :: "r"(m) : "memory");
}
__device__ __forceinline__ void mbar_expect_tx(uint32_t m, uint32_t bytes) {
    asm volatile("mbarrier.arrive.expect_tx.shared.b64 _, [%0], %1;" :: "r"(m), "r"(bytes) : "memory");
}
__device__ __forceinline__ void bulk_cp(uint32_t dst, const void* src, uint32_t bytes, uint32_t m) {
    asm volatile("cp.async.bulk.shared::cta.global.mbarrier::complete_tx::bytes [%0], [%1], %2, [%3];"
                 :: "r"(dst), "l"(src), "r"(bytes), "r"(m) : "memory");
}
__device__ __forceinline__ void mbar_wait(uint32_t m, uint32_t parity) {
    uint32_t done;
    asm volatile("{\n\t.reg .pred p;\n\t"
                 "mbarrier.try_wait.parity.acquire.cta.shared::cta.b64 p, [%1], %2;\n\t"
                 "selp.b32 %0, 1, 0, p;\n\t}"
                 : "=r"(done) : "r"(m), "r"(parity) : "memory");
    if (!done) {
        asm volatile("{\n\t.reg .pred P1;\n\t"
                     "W_%=:\n\t"
                     "mbarrier.try_wait.parity.acquire.cta.shared::cta.b64 P1, [%0], %1, 0x989680;\n\t"
                     "@P1 bra.uni D_%=;\n\t"
                     "bra.uni W_%=;\n\t"
                     "D_%=:\n\t}" :: "r"(m), "r"(parity) : "memory");
    }
}
__device__ __forceinline__ void mma_f16(float& d0, float& d1, float& d2, float& d3,
                                        uint32_t a0, uint32_t a1, uint32_t a2, uint32_t a3,
                                        uint32_t b0, uint32_t b1) {
    asm volatile("mma.sync.aligned.m16n8k16.row.col.f32.f16.f16.f32 "
                 "{%0,%1,%2,%3}, {%4,%5,%6,%7}, {%8,%9}, {%0,%1,%2,%3};"
                 : "+f"(d0), "+f"(d1), "+f"(d2), "+f"(d3)
                 : "r"(a0), "r"(a1), "r"(a2), "r"(a3), "r"(b0), "r"(b1));
}

__global__ __launch_bounds__(NTHREADS, 1)
void conv25d_mma_kernel(const float* __restrict__ inp, const float* __restrict__ dep,
                        const float* __restrict__ bias, const void* __restrict__ fptr,
                        float* __restrict__ out) {
    extern __shared__ char smem[];
    const uint32_t sb = smem_u32(smem);
    const int tid  = threadIdx.x;
    const int wid  = tid >> 5;
    const int lane = tid & 31;
    const int mw   = wid & 7;      // M warp: global px rows [mw*32, mw*32+32)
    const int nw   = wid >> 3;     // N warp: o cols [nw*32, nw*32+32)
    const int yl   = mw >> 2;      // local y row (0/1)
    const int pxl  = (mw & 3) * 32 + (lane >> 2);
    const int y0   = blockIdx.x * 2;
    const int b    = blockIdx.y;

    float*     s_d    = (float*)(smem + OFF_D);
    float*     s_lo   = (float*)(smem + OFF_LO);
    float*     s_hi   = (float*)(smem + OFF_HI);
    float*     s_bias = (float*)(smem + OFF_BIAS);
    uint32_t*  s_in   = (uint32_t*)(smem + OFF_IN);
    const uint32_t mb_full  = sb + OFF_FULL;
    const uint32_t mb_empty = sb + OFF_EMPTY;
    const uint32_t wsm      = sb + OFF_W;

    if (tid == 0) {
        for (int s = 0; s < NSLOT; s++) {
            mbar_init(mb_full + 8 * s, 1);
            mbar_init(mb_empty + 8 * s, 16);   // one arrive per warp
        }
    }
    __syncthreads();
    if (tid == 0) {
        asm volatile("fence.proxy.async.shared::cta;" ::: "memory");
        for (int t = 0; t < NSLOT; t++) {
            mbar_expect_tx(mb_full + 8 * t, TILE_BYTES);
            bulk_cp(wsm + t * TILE_BYTES, g_wf + t * 2048, TILE_BYTES, mb_full + 8 * t);
        }
    }

    // scalar f (int or float bits)
    unsigned fu = *reinterpret_cast<const unsigned*>(fptr);
    float fval = (fu > 0u && fu < (1u << 24)) ? (float)fu : __uint_as_float(fu);

    // depth rows y0-1..y0+2 (padded), bin bounds, bias
    const float* db = dep + (long)b * HH * WW;
    for (int i = tid; i < 4 * XPAD; i += NTHREADS) {
        int xx = i % XPAD, r = i / XPAD;
        int gx = xx - 1, gy = y0 + r - 1;
        float v = 0.f;
        if ((unsigned)gx < (unsigned)WW && (unsigned)gy < (unsigned)HH) v = db[gy * WW + gx];
        s_d[i] = v;
    }
    if (tid < 256) {
        int x = tid & 127, yy = y0 + (tid >> 7);
        float d0 = db[yy * WW + x];
        float s0 = __fdiv_rn(d0, fval);
        float hv = __fmul_rn(s0, 0.5f);
#pragma unroll
        for (int h = 0; h < 3; h++) {
            float z0 = __fadd_rn(d0, __fmul_rn((float)(h - 1), s0));
            s_lo[h * 256 + tid] = __fsub_rn(z0, hv);
            s_hi[h * 256 + tid] = __fadd_rn(z0, hv);
        }
    }
    if (tid < 64) s_bias[tid] = bias[tid];

    // stage input rows y0-1..y0+2 as half2 (c even/odd), zero halo
    const float* inb = inp + ((long)b * CIN) * HH * WW;
    for (int i = tid; i < 4 * 32 * XPAD; i += NTHREADS) {
        int xx = i % XPAD;
        int c2 = (i / XPAD) % 32;
        int r  = i / (XPAD * 32);
        int gx = xx - 1, gy = y0 + r - 1;
        uint32_t u = 0u;
        if ((unsigned)gx < (unsigned)WW && (unsigned)gy < (unsigned)HH) {
            float f0 = inb[((2 * c2) * HH + gy) * WW + gx];
            float f1 = inb[((2 * c2 + 1) * HH + gy) * WW + gx];
            __half2 p = __floats2half2_rn(f0, f1);
            u = *reinterpret_cast<uint32_t*>(&p);
        }
        s_in[i] = u;
    }
    __syncthreads();

    // per-thread bin bounds (global px = mw*32 + lane>>2 + i*8)
    float lo_r[3][4], hi_r[3][4];
#pragma unroll
    for (int i = 0; i < 4; i++) {
        int pg = mw * 32 + (lane >> 2) + i * 8;
#pragma unroll
        for (int h = 0; h < 3; h++) {
            lo_r[h][i] = s_lo[h * 256 + pg];
            hi_r[h][i] = s_hi[h * 256 + pg];
        }
    }

    float d[2][4][4];
#pragma unroll
    for (int mt = 0; mt < 2; mt++)
#pragma unroll
        for (int nt = 0; nt < 4; nt++)
#pragma unroll
            for (int r = 0; r < 4; r++) d[mt][nt][r] = 0.f;

#pragma unroll 1
    for (int tap = 0; tap < 9; tap++) {
        const int ky = tap / 3, kx = tap % 3;

        // wait all 3 h-tiles for this tap
        const uint2* bh[3];
#pragma unroll
        for (int h = 0; h < 3; h++) {
            int T = 3 * tap + h, s = T & 7;
            mbar_wait(mb_full + 8 * s, (T >> 3) & 1);
            bh[h] = (const uint2*)(smem + OFF_W + s * TILE_BYTES) + (nw * 4) * 32 + lane;
        }

        // per-row masks
        uint32_t msk[3][4];
#pragma unroll
        for (int i = 0; i < 4; i++) {
            float dw = s_d[(yl + ky) * XPAD + pxl + i * 8 + kx];
#pragma unroll
            for (int h = 0; h < 3; h++)
                msk[h][i] = (dw >= lo_r[h][i] && dw < hi_r[h][i]) ? 0xFFFFFFFFu : 0u;
        }

        const uint32_t* abase = s_in + (yl + ky) * 32 * XPAD + pxl + kx;

#pragma unroll 1
        for (int kc = 0; kc < 4; kc++) {
            const int c2 = kc * 8 + (lane & 3);
            uint32_t ar[2][4];
#pragma unroll
            for (int j = 0; j < 2; j++)
#pragma unroll
                for (int i = 0; i < 4; i++)
                    ar[j][i] = abase[(c2 + 4 * j) * XPAD + i * 8];

#pragma unroll
            for (int h = 0; h < 3; h++) {
                uint32_t am[2][4];
#pragma unroll
                for (int j = 0; j < 2; j++)
#pragma unroll
                    for (int i = 0; i < 4; i++)
                        am[j][i] = ar[j][i] & msk[h][i];

                const uint2* bp = bh[h] + (kc * 8) * 32;
                uint2 bf[4];
#pragma unroll
                for (int nt = 0; nt < 4; nt++) bf[nt] = bp[nt * 32];

#pragma unroll
                for (int mt = 0; mt < 2; mt++)
#pragma unroll
                    for (int nt = 0; nt < 4; nt++)
                        mma_f16(d[mt][nt][0], d[mt][nt][1], d[mt][nt][2], d[mt][nt][3],
                                am[0][2 * mt], am[0][2 * mt + 1],
                                am[1][2 * mt], am[1][2 * mt + 1],
                                bf[nt].x, bf[nt].y);
            }
        }

        // release slots
        if (lane == 0) {
#pragma unroll
            for (int h = 0; h < 3; h++) mbar_arrive(mb_empty + 8 * ((3 * tap + h) & 7));
        }
        // producer: keep ring 8 tiles ahead
        if (tid == 0) {
#pragma unroll
            for (int h = 0; h < 3; h++) {
                int T = 3 * tap + 8 + h;
                if (T > 26) break;
                int s = T & 7, r = T >> 3;
                mbar_wait(mb_empty + 8 * s, (r - 1) & 1);
                mbar_expect_tx(mb_full + 8 * s, TILE_BYTES);
                bulk_cp(wsm + s * TILE_BYTES, g_wf + T * 2048, TILE_BYTES, mb_full + 8 * s);
            }
        }
    }

    // epilogue: bias + store. out[b][o][y0+yl][px]
    float* ob = out + ((long)b * COUT * HH + (y0 + yl)) * WW;
#pragma unroll
    for (int mt = 0; mt < 2; mt++) {
        int pxr = (mw & 3) * 32 + mt * 16 + (lane >> 2);
#pragma unroll
        for (int nt = 0; nt < 4; nt++) {
            int o = nw * 32 + nt * 8 + 2 * (lane & 3);
            float b0 = s_bias[o], b1 = s_bias[o + 1];
            float* p0 = ob + (long)o * HH * WW + pxr;
            float* p1 = p0 + HH * WW;
            p0[0] = d[mt][nt][0] + b0;
            p1[0] = d[mt][nt][1] + b1;
            p0[8] = d[mt][nt][2] + b0;
            p1[8] = d[mt][nt][3] + b1;
        }
    }
}

extern "C" void kernel_launch(void* const* d_in, const int* in_sizes, int n_in,
                              void* d_out, int out_size) {
    const float* inputs = (const float*)d_in[0];
    const float* depth  = (const float*)d_in[1];
    const float* weight = (const float*)d_in[2];
    const float* bias   = (const float*)d_in[3];
    const void*  f      = d_in[4];
    float* out = (float*)d_out;

    prep_w_kernel<<<(27 * 2048 + 255) / 256, 256>>>(weight);

    cudaFuncSetAttribute(conv25d_mma_kernel, cudaFuncAttributeMaxDynamicSharedMemorySize,
                         SMEM_TOTAL);
    dim3 grid(HH / 2, BB);
    conv25d_mma_kernel<<<grid, NTHREADS, SMEM_TOTAL>>>(inputs, depth, bias, f, out);
}

// round 7
// speedup vs baseline: 7.3951x; 1.0094x over previous
#include <cuda_runtime.h>
#include <cuda_fp16.h>
#include <cstdint>

#define CIN 64
#define COUT 64
#define HH 128
#define WW 128
#define BB 4
#define NTHREADS 512
#define XPAD 136            // x extent incl. halo/pad
#define XPC2 36             // words per x in s_in (32 c2 + 4 pad) -> ldmatrix conflict-free
#define NSLOT 8             // weight ring slots (8 KB h-tiles)
#define TILE_BYTES 8192

// ---- smem byte offsets ----
#define OFF_FULL  0         // 8 x 8B
#define OFF_EMPTY 64        // 8 x 8B
#define OFF_D     128       // 4 x 136 floats
#define OFF_LO    2304      // 3 x 256 floats
#define OFF_HI    5376      // 3 x 256 floats
#define OFF_BIAS  8448      // 64 floats
#define OFF_IN    8704      // 4 rows x 136 x x 36 words = 78336 B  [r][x][c2]
#define OFF_W     87040     // 8 slots x 8192 B
#define SMEM_TOTAL 152576

// Fragment-ordered f16 weights: [tile=tap*3+h][kc4][nt8][lane32][j2] (u32 = half2)
__device__ uint32_t g_wf[27 * 2048];

__global__ void prep_w_kernel(const float* __restrict__ w) {
    int idx = blockIdx.x * blockDim.x + threadIdx.x;
    if (idx >= 27 * 2048) return;
    int j    = idx & 1;
    int lane = (idx >> 1) & 31;
    int nt   = (idx >> 6) & 7;
    int kc   = (idx >> 9) & 3;
    int tile = idx >> 11;
    int h = tile % 3, tap = tile / 3;
    int k0 = kc * 16 + (lane & 3) * 2 + j * 8;
    int o  = nt * 8 + (lane >> 2);
    // source layout: [h][o][c][ky][kx]
    float v0 = w[(((h * COUT + o) * CIN + k0) * 9) + tap];
    float v1 = w[(((h * COUT + o) * CIN + k0 + 1) * 9) + tap];
    __half2 p = __floats2half2_rn(v0, v1);
    g_wf[idx] = *reinterpret_cast<uint32_t*>(&p);
}

// ---- PTX helpers ----
__device__ __forceinline__ uint32_t smem_u32(const void* p) {
    uint32_t a;
    asm("{ .reg .u64 t; cvta.to.shared.u64 t, %1; cvt.u32.u64 %0, t; }" : "=r"(a) : "l"(p));
    return a;
}
__device__ __forceinline__ void mbar_init(uint32_t m, uint32_t cnt) {
    asm volatile("mbarrier.init.shared.b64 [%0], %1;" :: "r"(m), "r"(cnt) : "memory");
}
__device__ __forceinline__ void mbar_arrive(uint32_t m) {
    asm volatile("mbarrier.arrive.shared.b64 _, [%0];" :: "r"(m) : "memory");
}
__device__ __forceinline__ void mbar_expect_tx(uint32_t m, uint32_t bytes) {
    asm volatile("mbarrier.arrive.expect_tx.shared.b64 _, [%0], %1;" :: "r"(m), "r"(bytes) : "memory");
}
__device__ __forceinline__ void bulk_cp(uint32_t dst, const void* src, uint32_t bytes, uint32_t m) {
    asm volatile("cp.async.bulk.shared::cta.global.mbarrier::complete_tx::bytes [%0], [%1], %2, [%3];"
                 :: "r"(dst), "l"(src), "r"(bytes), "r"(m) : "memory");
}
__device__ __forceinline__ void mbar_wait(uint32_t m, uint32_t parity) {
    uint32_t done;
    asm volatile("{\n\t.reg .pred p;\n\t"
                 "mbarrier.try_wait.parity.acquire.cta.shared::cta.b64 p, [%1], %2;\n\t"
                 "selp.b32 %0, 1, 0, p;\n\t}"
                 : "=r"(done) : "r"(m), "r"(parity) : "memory");
    if (!done) {
        asm volatile("{\n\t.reg .pred P1;\n\t"
                     "W_%=:\n\t"
                     "mbarrier.try_wait.parity.acquire.cta.shared::cta.b64 P1, [%0], %1, 0x989680;\n\t"
                     "@P1 bra.uni D_%=;\n\t"
                     "bra.uni W_%=;\n\t"
                     "D_%=:\n\t}" :: "r"(m), "r"(parity) : "memory");
    }
}
__device__ __forceinline__ void ldmx4(uint32_t* r, uint32_t addr) {
    asm volatile("ldmatrix.sync.aligned.m8n8.x4.shared.b16 {%0,%1,%2,%3}, [%4];"
                 : "=r"(r[0]), "=r"(r[1]), "=r"(r[2]), "=r"(r[3]) : "r"(addr));
}
__device__ __forceinline__ void mma_f16(float& d0, float& d1, float& d2, float& d3,
                                        uint32_t a0, uint32_t a1, uint32_t a2, uint32_t a3,
                                        uint32_t b0, uint32_t b1) {
    asm volatile("mma.sync.aligned.m16n8k16.row.col.f32.f16.f16.f32 "
                 "{%0,%1,%2,%3}, {%4,%5,%6,%7}, {%8,%9}, {%0,%1,%2,%3};"
                 : "+f"(d0), "+f"(d1), "+f"(d2), "+f"(d3)
                 : "r"(a0), "r"(a1), "r"(a2), "r"(a3), "r"(b0), "r"(b1));
}

__global__ __launch_bounds__(NTHREADS, 1)
void conv25d_mma_kernel(const float* __restrict__ inp, const float* __restrict__ dep,
                        const float* __restrict__ bias, const void* __restrict__ fptr,
                        float* __restrict__ out) {
    extern __shared__ char smem[];
    const uint32_t sb = smem_u32(smem);
    const int tid  = threadIdx.x;
    const int wid  = tid >> 5;
    const int lane = tid & 31;
    const int mw   = wid & 7;      // M warp
    const int nw   = wid >> 3;     // N warp
    const int yl   = mw >> 2;      // local y row (0/1)
    const int y0   = blockIdx.x * 2;
    const int b    = blockIdx.y;

    float*     s_d    = (float*)(smem + OFF_D);
    float*     s_lo   = (float*)(smem + OFF_LO);
    float*     s_hi   = (float*)(smem + OFF_HI);
    float*     s_bias = (float*)(smem + OFF_BIAS);
    uint32_t*  s_in   = (uint32_t*)(smem + OFF_IN);
    const uint32_t mb_full  = sb + OFF_FULL;
    const uint32_t mb_empty = sb + OFF_EMPTY;
    const uint32_t wsm      = sb + OFF_W;

    if (tid == 0) {
        for (int s = 0; s < NSLOT; s++) {
            mbar_init(mb_full + 8 * s, 1);
            mbar_init(mb_empty + 8 * s, 16);
        }
    }
    __syncthreads();
    if (tid == 0) {
        asm volatile("fence.proxy.async.shared::cta;" ::: "memory");
        for (int t = 0; t < NSLOT; t++) {
            mbar_expect_tx(mb_full + 8 * t, TILE_BYTES);
            bulk_cp(wsm + t * TILE_BYTES, g_wf + t * 2048, TILE_BYTES, mb_full + 8 * t);
        }
    }

    // scalar f (int or float bits)
    unsigned fu = *reinterpret_cast<const unsigned*>(fptr);
    float fval = (fu > 0u && fu < (1u << 24)) ? (float)fu : __uint_as_float(fu);

    // depth rows y0-1..y0+2 (padded), bin bounds, bias
    const float* db = dep + (long)b * HH * WW;
    for (int i = tid; i < 4 * XPAD; i += NTHREADS) {
        int xx = i % XPAD, r = i / XPAD;
        int gx = xx - 1, gy = y0 + r - 1;
        float v = 0.f;
        if ((unsigned)gx < (unsigned)WW && (unsigned)gy < (unsigned)HH) v = db[gy * WW + gx];
        s_d[i] = v;
    }
    if (tid < 256) {
        int x = tid & 127, yy = y0 + (tid >> 7);
        float d0 = db[yy * WW + x];
        float s0 = __fdiv_rn(d0, fval);
        float hv = __fmul_rn(s0, 0.5f);
#pragma unroll
        for (int h = 0; h < 3; h++) {
            float z0 = __fadd_rn(d0, __fmul_rn((float)(h - 1), s0));
            s_lo[h * 256 + tid] = __fsub_rn(z0, hv);
            s_hi[h * 256 + tid] = __fadd_rn(z0, hv);
        }
    }
    if (tid < 64) s_bias[tid] = bias[tid];

    // stage input rows y0-1..y0+2 as half2, layout [r][x][c2] (k-contiguous for ldmatrix)
    const float* inb = inp + ((long)b * CIN) * HH * WW;
    for (int i = tid; i < 4 * 32 * XPAD; i += NTHREADS) {
        int xx = i % XPAD;
        int c2 = (i / XPAD) % 32;
        int r  = i / (XPAD * 32);
        int gx = xx - 1, gy = y0 + r - 1;
        uint32_t u = 0u;
        if ((unsigned)gx < (unsigned)WW && (unsigned)gy < (unsigned)HH) {
            float f0 = inb[((2 * c2) * HH + gy) * WW + gx];
            float f1 = inb[((2 * c2 + 1) * HH + gy) * WW + gx];
            __half2 p = __floats2half2_rn(f0, f1);
            u = *reinterpret_cast<uint32_t*>(&p);
        }
        s_in[(r * XPAD + xx) * XPC2 + c2] = u;
    }
    __syncthreads();

    // ldmatrix lane address components
    const int t4     = lane >> 3;                        // tile 0..3
    const int p_lane = (mw & 3) * 32 + (t4 & 1) * 8 + (lane & 7);
    const int c2off  = (t4 >> 1) * 4;                    // k-half
    const int pxl4   = (mw & 3) * 32 + (lane >> 2);      // mask-owner pixel (row within y)
    const int pgb    = mw * 32 + (lane >> 2);            // bound index (2 rows x 128)

    float d[2][4][4];
#pragma unroll
    for (int mt = 0; mt < 2; mt++)
#pragma unroll
        for (int nt = 0; nt < 4; nt++)
#pragma unroll
            for (int r = 0; r < 4; r++) d[mt][nt][r] = 0.f;

#pragma unroll 1
    for (int tap = 0; tap < 9; tap++) {
        const int ky = tap / 3, kx = tap % 3;

        // wait the 3 h-tiles for this tap
        const uint2* bh[3];
#pragma unroll
        for (int h = 0; h < 3; h++) {
            int T = 3 * tap + h, s = T & 7;
            mbar_wait(mb_full + 8 * s, (T >> 3) & 1);
            bh[h] = (const uint2*)(smem + OFF_W + s * TILE_BYTES) + (nw * 4) * 32 + lane;
        }

        // hoist ALL of this tap's A fragments: 8 ldmatrix.x4 back-to-back
        uint32_t A[4][2][4];
        const uint32_t abase = sb + OFF_IN +
            4u * (uint32_t)(((yl + ky) * XPAD + p_lane + kx) * XPC2 + c2off);
#pragma unroll
        for (int kc = 0; kc < 4; kc++)
#pragma unroll
            for (int mt = 0; mt < 2; mt++)
                ldmx4(A[kc][mt], abase + 4u * (uint32_t)(mt * 16 * XPC2 + kc * 8));

        // masks for this tap (from smem; no persistent reg cache)
        uint32_t msk[3][4];
#pragma unroll
        for (int i = 0; i < 4; i++) {
            float dw = s_d[(yl + ky) * XPAD + pxl4 + i * 8 + kx];
#pragma unroll
            for (int h = 0; h < 3; h++) {
                float lo = s_lo[h * 256 + pgb + i * 8];
                float hi = s_hi[h * 256 + pgb + i * 8];
                msk[h][i] = (dw >= lo && dw < hi) ? 0xFFFFFFFFu : 0u;
            }
        }

#pragma unroll
        for (int h = 0; h < 3; h++) {
#pragma unroll
            for (int kc = 0; kc < 4; kc++) {
                const uint2* bp = bh[h] + (kc * 8) * 32;
                uint2 bf[4];
#pragma unroll
                for (int nt = 0; nt < 4; nt++) bf[nt] = bp[nt * 32];
#pragma unroll
                for (int mt = 0; mt < 2; mt++) {
                    uint32_t a0 = A[kc][mt][0] & msk[h][2 * mt];
                    uint32_t a1 = A[kc][mt][1] & msk[h][2 * mt + 1];
                    uint32_t a2 = A[kc][mt][2] & msk[h][2 * mt];
                    uint32_t a3 = A[kc][mt][3] & msk[h][2 * mt + 1];
#pragma unroll
                    for (int nt = 0; nt < 4; nt++)
                        mma_f16(d[mt][nt][0], d[mt][nt][1], d[mt][nt][2], d[mt][nt][3],
                                a0, a1, a2, a3, bf[nt].x, bf[nt].y);
                }
            }
        }

        // release slots
        if (lane == 0) {
#pragma unroll
            for (int h = 0; h < 3; h++) mbar_arrive(mb_empty + 8 * ((3 * tap + h) & 7));
        }
        // producer: keep ring 8 tiles ahead
        if (tid == 0) {
#pragma unroll
            for (int h = 0; h < 3; h++) {
                int T = 3 * tap + 8 + h;
                if (T > 26) break;
                int s = T & 7, r = T >> 3;
                mbar_wait(mb_empty + 8 * s, (r - 1) & 1);
                mbar_expect_tx(mb_full + 8 * s, TILE_BYTES);
                bulk_cp(wsm + s * TILE_BYTES, g_wf + T * 2048, TILE_BYTES, mb_full + 8 * s);
            }
        }
    }

    // epilogue: bias + store. out[b][o][y0+yl][px]
    float* ob = out + ((long)b * COUT * HH + (y0 + yl)) * WW;
#pragma unroll
    for (int mt = 0; mt < 2; mt++) {
        int pxr = (mw & 3) * 32 + mt * 16 + (lane >> 2);
#pragma unroll
        for (int nt = 0; nt < 4; nt++) {
            int o = nw * 32 + nt * 8 + 2 * (lane & 3);
            float b0 = s_bias[o], b1 = s_bias[o + 1];
            float* p0 = ob + (long)o * HH * WW + pxr;
            float* p1 = p0 + HH * WW;
            p0[0] = d[mt][nt][0] + b0;
            p1[0] = d[mt][nt][1] + b1;
            p0[8] = d[mt][nt][2] + b0;
            p1[8] = d[mt][nt][3] + b1;
        }
    }
}

extern "C" void kernel_launch(void* const* d_in, const int* in_sizes, int n_in,
                              void* d_out, int out_size) {
    const float* inputs = (const float*)d_in[0];
    const float* depth  = (const float*)d_in[1];
    const float* weight = (const float*)d_in[2];
    const float* bias   = (const float*)d_in[3];
    const void*  f      = d_in[4];
    float* out = (float*)d_out;

    prep_w_kernel<<<(27 * 2048 + 255) / 256, 256>>>(weight);

    cudaFuncSetAttribute(conv25d_mma_kernel, cudaFuncAttributeMaxDynamicSharedMemorySize,
                         SMEM_TOTAL);
    dim3 grid(HH / 2, BB);
    conv25d_mma_kernel<<<grid, NTHREADS, SMEM_TOTAL>>>(inputs, depth, bias, f, out);
}